// round 10
// baseline (speedup 1.0000x reference)
#include <cuda_runtime.h>
#include <cooperative_groups.h>
#include <cstdint>

namespace cg = cooperative_groups;

#define T_STEPS 2048
#define V_SZ    2048
#define G_SZ    24
#define K_SZ    512
#define CLUSTER_N 8
#define JPB     64              // columns of Wh per CTA
#define NCLUSTERS 12            // 12 clusters * 2 groups * 2 recs = 48
#define NBLOCKS (NCLUSTERS * CLUSTER_N)
#define THREADS_RNN 256
#define BLK_F   132             // padded source block: 128 data floats + 4 pad
#define SLICE_B 512             // copied bytes per (src CTA, group): 2 recs x 64 cols
#define PHASE_TX ((CLUSTER_N - 1) * SLICE_B)   // 3584 B remote per (group,buf) phase

// ---------------- mbarrier helpers ----------------
#define MBARRIER_INIT(addr, count) \
    asm volatile("mbarrier.init.shared.b64 [%0], %1;" :: "r"((uint32_t)(addr)), "r"((uint32_t)(count)) : "memory")

#define MBARRIER_EXPECT_TX(addr, bytes) \
    asm volatile("mbarrier.arrive.expect_tx.shared.b64 _, [%0], %1;" :: "r"((uint32_t)(addr)), "r"((uint32_t)(bytes)) : "memory")

#define MBARRIER_ARRIVE(addr) \
    asm volatile("mbarrier.arrive.shared.b64 _, [%0];" :: "r"((uint32_t)(addr)) : "memory")

#define MBARRIER_WAIT_PARITY(mbar_smem_addr, phase_parity) do { \
    uint32_t _mbar = (uint32_t)(mbar_smem_addr); \
    uint32_t _parity = (uint32_t)(phase_parity); \
    uint32_t _done; \
    asm volatile( \
        "{\n\t" \
        ".reg .pred p;\n\t" \
        "mbarrier.try_wait.parity.acquire.cta.shared::cta.b64 p, [%1], %2;\n\t" \
        "selp.b32 %0, 1, 0, p;\n\t" \
        "}" \
        : "=r"(_done) : "r"(_mbar), "r"(_parity) : "memory"); \
    if (!_done) { \
        asm volatile( \
            "{\n\t" \
            ".reg .pred P1;\n\t" \
            "WAIT_LOOP_%=:\n\t" \
            "mbarrier.try_wait.parity.acquire.cta.shared::cta.b64 P1, [%0], %1, 0x989680;\n\t" \
            "@P1 bra.uni WAIT_DONE_%=;\n\t" \
            "bra.uni WAIT_LOOP_%=;\n\t" \
            "WAIT_DONE_%=:\n\t" \
            "}" \
            :: "r"(_mbar), "r"(_parity) : "memory"); \
    } \
} while(0)

__device__ __forceinline__ uint32_t s2u(const void* p) {
    uint32_t a;
    asm("{ .reg .u64 t; cvta.to.shared.u64 t, %1; cvt.u32.u64 %0, t; }" : "=r"(a) : "l"(p));
    return a;
}

__device__ __forceinline__ void ffma2(unsigned long long& acc,
                                      unsigned long long h2,
                                      unsigned long long w2) {
    asm("fma.rn.f32x2 %0, %1, %2, %0;" : "+l"(acc) : "l"(h2), "l"(w2));
}

__device__ __forceinline__ unsigned long long packf2(float lo, float hi) {
    unsigned long long r;
    asm("mov.b64 %0, {%1, %2};" : "=l"(r) : "f"(lo), "f"(hi));
    return r;
}

__device__ __forceinline__ float sum2(unsigned long long acc) {
    float lo, hi;
    asm("mov.b64 {%0, %1}, %2;" : "=f"(lo), "=f"(hi) : "l"(acc));
    return lo + hi;
}

// Scratch (no cudaMalloc allowed)
__device__ float g_P[V_SZ * K_SZ];       // P = W_e @ Wx + b   (V, K)
__device__ int   g_idx[T_STEPS * G_SZ];  // idx[t,g] = perms[g, token_t]

// ---------------------------------------------------------------------------
// Kernel 1 (fused): token recovery + P = W_e @ Wx + b
// ---------------------------------------------------------------------------
__global__ void __launch_bounds__(256)
prep_kernel(const float* __restrict__ seq,
            const int* __restrict__ perms,
            const float* __restrict__ We,
            const float* __restrict__ Wx,
            const float* __restrict__ b) {
    int tid = threadIdx.x;
    int wid = tid >> 5, lane = tid & 31;

    // ---- token part: warp wid scans one one-hot row ----
    {
        int bid = blockIdx.y * gridDim.x + blockIdx.x;   // 0..255
        int row = bid * 8 + wid;                          // 0..2047
        const float4* r4 = (const float4*)(seq + (size_t)row * V_SZ) + lane * 16;
        int found = -1;
        #pragma unroll
        for (int i = 0; i < 16; i++) {
            float4 v = r4[i];
            int base = lane * 64 + i * 4;
            if (v.x > 0.5f) found = base;
            if (v.y > 0.5f) found = base + 1;
            if (v.z > 0.5f) found = base + 2;
            if (v.w > 0.5f) found = base + 3;
        }
        int tok = __reduce_max_sync(0xffffffffu, found);
        if (lane < G_SZ)
            g_idx[row * G_SZ + lane] = perms[lane * V_SZ + tok];
    }

    // ---- GEMM part ----
    __shared__ float sA[64][17];
    __shared__ float sB[16][68];
    int tx = tid & 15, ty = tid >> 4;
    int row0 = blockIdx.y * 64;
    int col0 = blockIdx.x * 64;
    float acc[4][4] = {};

    for (int kc = 0; kc < K_SZ; kc += 16) {
        {
            int v  = tid >> 2;
            int c4 = (tid & 3) * 4;
            float4 av = *(const float4*)&We[(size_t)(row0 + v) * K_SZ + kc + c4];
            sA[v][c4 + 0] = av.x; sA[v][c4 + 1] = av.y;
            sA[v][c4 + 2] = av.z; sA[v][c4 + 3] = av.w;
        }
        {
            int c  = tid >> 4;
            int k4 = (tid & 15) * 4;
            float4 bv = *(const float4*)&Wx[(size_t)(kc + c) * K_SZ + col0 + k4];
            sB[c][k4 + 0] = bv.x; sB[c][k4 + 1] = bv.y;
            sB[c][k4 + 2] = bv.z; sB[c][k4 + 3] = bv.w;
        }
        __syncthreads();
        #pragma unroll
        for (int cc = 0; cc < 16; cc++) {
            float ar[4], br[4];
            #pragma unroll
            for (int u = 0; u < 4; u++) ar[u] = sA[ty * 4 + u][cc];
            #pragma unroll
            for (int ww = 0; ww < 4; ww++) br[ww] = sB[cc][tx * 4 + ww];
            #pragma unroll
            for (int u = 0; u < 4; u++)
                #pragma unroll
                for (int ww = 0; ww < 4; ww++)
                    acc[u][ww] = fmaf(ar[u], br[ww], acc[u][ww]);
        }
        __syncthreads();
    }
    #pragma unroll
    for (int u = 0; u < 4; u++) {
        int r = row0 + ty * 4 + u;
        #pragma unroll
        for (int ww = 0; ww < 4; ww++) {
            int c = col0 + tx * 4 + ww;
            g_P[(size_t)r * K_SZ + c] = acc[u][ww] + b[c];
        }
    }
}

// ---------------------------------------------------------------------------
// Kernel 2: persistent cluster recurrence. Column-split, padded h, NO block
// syncs in the main loop. Group barrier: count 9 (8 warp arrivals + 1 re-arm
// arrive) + expect_tx 3584B (7 remote copies) — covers local stores AND remote
// data. Local barrier (count 8) gates warp 0's copy issue only.
// ---------------------------------------------------------------------------
__device__ __forceinline__ int tpos(int s, int dir) {
    return dir ? ((s < T_STEPS - 1) ? (T_STEPS - 2 - s) : (T_STEPS - 1)) : s;
}

struct __align__(16) SmemRNN {
    float h[2][2][CLUSTER_N][BLK_F];   // 16896 B [grp][buf][src][132]
    unsigned long long bar[4];         //    32 B [grp*2+buf] count=9 + tx
    unsigned long long lbar[2];        //    16 B [grp]       count=8
};

__global__ void __launch_bounds__(THREADS_RNN, 1) __cluster_dims__(CLUSTER_N, 1, 1)
rnn_kernel(const float* __restrict__ Wh,
           float* __restrict__ out,
           int writeHt) {
    __shared__ SmemRNN sm;
    cg::cluster_group cluster = cg::this_cluster();
    const int rank = (int)cluster.block_rank();
    const int cid  = blockIdx.x / CLUSTER_N;
    const int tid  = threadIdx.x;
    const int lane = tid & 31;
    const int w    = tid >> 5;
    const int jg   = rank * JPB;
    const int jc   = jg + w * 8 + (lane & 7);   // this lane's output column
    const int seg  = lane >> 3;                 // row segment: rows [seg*128, +128)

    const uint32_t bar_base  = s2u(&sm.bar[0]);
    const uint32_t lbar_base = s2u(&sm.lbar[0]);
    if (tid == 0) {
        #pragma unroll
        for (int b2 = 0; b2 < 4; b2++) MBARRIER_INIT(bar_base + b2 * 8, 9);
        MBARRIER_INIT(lbar_base + 0, 8);
        MBARRIER_INIT(lbar_base + 8, 8);
    }
    __syncthreads();
    if (tid == 0) {   // initial arm: the "9th" arrive for phase 0 of each bar
        #pragma unroll
        for (int b2 = 0; b2 < 4; b2++) MBARRIER_EXPECT_TX(bar_base + b2 * 8, PHASE_TX);
    }

    // ---- weights: rows [seg*128, +128) of column jc, packed row-pairs ----
    unsigned long long w2[64];
    {
        const float* wb = Wh + jc;
        #pragma unroll
        for (int k = 0; k < 2; k++)
            #pragma unroll
            for (int m = 0; m < 32; m++) {
                int r = seg * 128 + k * 64 + 2 * m;
                w2[k * 32 + m] = packf2(wb[(size_t)r * K_SZ],
                                        wb[(size_t)(r + 1) * K_SZ]);
            }
    }
    // zero all h buffers (incl. padding)
    for (int i = tid; i < 2 * 2 * CLUSTER_N * BLK_F; i += THREADS_RNN)
        (&sm.h[0][0][0][0])[i] = 0.f;

    // ---- x in registers: lanes 16..23 hold col w*8+(lane-16) for both dirs ----
    const bool xlane = (lane >= 16 && lane < 24);
    const int  xcol  = jg + w * 8 + (lane - 16);
    float xF[2] = {0.f, 0.f}, xR[2] = {0.f, 0.f};
    int   tF[2] = {0, 0},     tR[2] = {0, 0};
    if (xlane) {
        #pragma unroll
        for (int g = 0; g < 2; g++) {
            int gg = cid * 2 + g;
            xF[g] = g_P[(size_t)g_idx[0 * G_SZ + gg] * K_SZ + xcol];
            xR[g] = g_P[(size_t)g_idx[(T_STEPS - 2) * G_SZ + gg] * K_SZ + xcol];
            tF[g] = g_idx[1 * G_SZ + gg];
            tR[g] = g_idx[(T_STEPS - 3) * G_SZ + gg];
        }
    }
    __syncthreads();
    cluster.sync();   // barriers armed cluster-wide before any copies fly

    // copy destinations: warp 0 lane d (<7) handles dest rank skipping self
    uint32_t rem_h_t = 0, rem_bar_t = 0;
    const uint32_t my_h = s2u(&sm.h[0][0][0][0]);
    if (w == 0 && lane < CLUSTER_N - 1) {
        int dst = lane + (lane >= rank ? 1 : 0);
        asm("mapa.shared::cluster.u32 %0, %1, %2;" : "=r"(rem_h_t)   : "r"(my_h),     "r"(dst));
        asm("mapa.shared::cluster.u32 %0, %1, %2;" : "=r"(rem_bar_t) : "r"(bar_base), "r"(dst));
    }

    const size_t hb0 = (size_t)T_STEPS * G_SZ * 2 * K_SZ;
    int p = 0;
    for (int s = 0; s < T_STEPS; s++) {
        const bool last = (s == T_STEPS - 1);
        const int np = p ^ 1;
        const int wpar = ((s >> 1) + 1 - (s & 1)) & 1;

        #pragma unroll
        for (int g = 0; g < 2; g++) {
            const int gg = cid * 2 + g;

            // ---- issue x gathers for step s+1 (hidden under mainloop) ----
            float xFn = 0.f, xRn = 0.f;
            if (xlane && !last) {
                xFn = g_P[(size_t)tF[g] * K_SZ + xcol];
                xRn = g_P[(size_t)tR[g] * K_SZ + xcol];
            }

            // ---- wait: local stores + remote copies of this group ----
            const uint32_t mybar = bar_base + (uint32_t)((g * 2 + p) * 8);
            if (s > 0) {
                MBARRIER_WAIT_PARITY(mybar, wpar);
                if (tid == 0 && s + 2 < T_STEPS)
                    MBARRIER_EXPECT_TX(mybar, PHASE_TX);   // 9th arrive + tx, next phase
            }

            // ---- mainloop: rows [seg*128,+128) of col jc, both recs ----
            const float* hgb = &sm.h[g][p][0][0];
            unsigned long long a0e = 0ull, a0o = 0ull, a1e = 0ull, a1o = 0ull;
            #pragma unroll
            for (int k = 0; k < 2; k++) {
                const float* b0 = hgb + (2 * seg + k) * BLK_F;   // rec0 base
                const float* b1 = b0 + 64;                       // rec1 base
                #pragma unroll
                for (int m = 0; m < 16; m++) {
                    ulonglong2 H0 = *(const ulonglong2*)(b0 + 4 * m);
                    ulonglong2 H1 = *(const ulonglong2*)(b1 + 4 * m);
                    ffma2(a0e, H0.x, w2[k * 32 + 2 * m]);
                    ffma2(a0o, H0.y, w2[k * 32 + 2 * m + 1]);
                    ffma2(a1e, H1.x, w2[k * 32 + 2 * m]);
                    ffma2(a1o, H1.y, w2[k * 32 + 2 * m + 1]);
                }
            }
            float a0 = sum2(a0e) + sum2(a0o);
            float a1 = sum2(a1e) + sum2(a1o);
            // fold x into the reduce (seg-2 lanes hold x for col lane&7)
            if (xlane) { a0 += xF[g]; a1 += xR[g]; }
            a0 += __shfl_xor_sync(0xffffffffu, a0, 8);
            a0 += __shfl_xor_sync(0xffffffffu, a0, 16);
            a1 += __shfl_xor_sync(0xffffffffu, a1, 8);
            a1 += __shfl_xor_sync(0xffffffffu, a1, 16);

            // ---- tanh split: lanes 0..7 -> rec0, lanes 8..15 -> rec1 ----
            float v = 0.f;
            if (lane < 16) {
                v = tanhf(lane < 8 ? a0 : a1);
                if (!last) {
                    float* dstp = &sm.h[g][np][rank][0];
                    dstp[(lane >> 3) * 64 + w * 8 + (lane & 7)] = v;
                    asm volatile("fence.proxy.async.shared::cta;" ::: "memory");
                }
            }
            __syncwarp();
            if (!last) {
                if (lane == 0) {
                    MBARRIER_ARRIVE(bar_base + (uint32_t)((g * 2 + np) * 8));
                    MBARRIER_ARRIVE(lbar_base + (uint32_t)(g * 8));
                }
                if (w == 0) {
                    // warp 0: wait all 8 local-store arrivals, issue 7 copies
                    MBARRIER_WAIT_PARITY(lbar_base + (uint32_t)(g * 8), s & 1);
                    if (lane < CLUSTER_N - 1) {
                        uint32_t off = (uint32_t)((g * 2 + np) * CLUSTER_N + rank) * (BLK_F * 4);
                        uint32_t rb  = rem_bar_t + (uint32_t)((g * 2 + np) * 8);
                        asm volatile(
                            "cp.async.bulk.shared::cluster.shared::cta.mbarrier::complete_tx::bytes "
                            "[%0], [%1], %2, [%3];"
                            :: "r"(rem_h_t + off), "r"(my_h + off), "r"(SLICE_B), "r"(rb) : "memory");
                    }
                }
            }

            // ---- tail: global out stores + x register rotation ----
            if (lane < 16) {
                int rrec = lane >> 3;
                int tt = tpos(s, rrec);
                out[((size_t)tt * G_SZ + gg) * (2 * K_SZ) + rrec * K_SZ + jc] = v;
                if (last && writeHt)
                    out[hb0 + (size_t)gg * (2 * K_SZ) + rrec * K_SZ + jc] = v;
            } else if (xlane) {
                xF[g] = xFn;  xR[g] = xRn;
                if (s + 2 < T_STEPS) {
                    tF[g] = g_idx[tpos(s + 2, 0) * G_SZ + gg];
                    tR[g] = g_idx[tpos(s + 2, 1) * G_SZ + gg];
                }
            }
        }
        p = np;
    }
    cluster.sync();   // no CTA exits while peer copies may be in flight
}

// ---------------------------------------------------------------------------
extern "C" void kernel_launch(void* const* d_in, const int* in_sizes, int n_in,
                              void* d_out, int out_size) {
    const float* seq   = (const float*)d_in[0];  // (T, V)
    const int*   perms = (const int*)  d_in[1];  // (G, V)
    const float* We    = (const float*)d_in[2];  // (V, K)
    const float* Wx    = (const float*)d_in[3];  // (K, K)
    const float* Wh    = (const float*)d_in[4];  // (K, K)
    const float* b     = (const float*)d_in[5];  // (K,)
    float* out = (float*)d_out;
    (void)in_sizes; (void)n_in;

    long long need = (long long)T_STEPS * G_SZ * 2 * K_SZ + (long long)G_SZ * 2 * K_SZ;
    int writeHt = ((long long)out_size >= need) ? 1 : 0;

    dim3 ggrid(K_SZ / 64, V_SZ / 64);   // (8, 32) = 256 blocks
    prep_kernel<<<ggrid, 256>>>(seq, perms, We, Wx, b);
    rnn_kernel<<<NBLOCKS, THREADS_RNN>>>(Wh, out, writeHt);
}